// round 17
// baseline (speedup 1.0000x reference)
#include <cuda_runtime.h>
#include <cuda_bf16.h>
#include <math.h>
#include <stdint.h>

// Problem constants
#define B_SZ   8192
#define D_IN   1024
#define E_EXP  8
#define T_TASK 4
#define H1_SZ  1024
#define H2_SZ  512
#define H3_SZ  256

// Scratch (device globals: allocation-free, graph-capture safe)
static __device__ float g_h1[(long)B_SZ * E_EXP * H1_SZ];       // 256 MB
static __device__ float g_h2[(long)B_SZ * E_EXP * H2_SZ];       // 128 MB
static __device__ float g_h3[(long)B_SZ * E_EXP * H3_SZ];       //  64 MB
static __device__ float g_gates[(long)B_SZ * E_EXP * T_TASK];   //   1 MB
static __device__ float g_xr [(long)B_SZ * D_IN];               //  32 MB  x  (tf32-rounded)
static __device__ float g_w1r[(long)E_EXP * D_IN * H1_SZ];      //  32 MB  W1 (tf32-rounded)
static __device__ float g_w2r[(long)E_EXP * H1_SZ * H2_SZ];     //  16 MB  W2 (tf32-rounded)
static __device__ float g_w3r[(long)E_EXP * H2_SZ * H3_SZ];     //   4 MB  W3 (tf32-rounded)

__device__ __forceinline__ float rna_tf32(float x) {
    uint32_t r;
    asm("cvt.rna.tf32.f32 %0, %1;" : "=r"(r) : "f"(x));
    return __uint_as_float(r);
}

__device__ __forceinline__ uint32_t smem_u32(const void* p) {
    uint32_t a;
    asm("{ .reg .u64 t; cvta.to.shared.u64 t, %1; cvt.u32.u64 %0, t; }" : "=r"(a) : "l"(p));
    return a;
}

__device__ __forceinline__ void cp_async16(uint32_t dst, const void* src) {
    asm volatile("cp.async.cg.shared.global [%0], [%1], 16;"
                 :: "r"(dst), "l"(src) : "memory");
}
#define CP_COMMIT()  asm volatile("cp.async.commit_group;" ::: "memory")
#define CP_WAIT(n)   asm volatile("cp.async.wait_group %0;" :: "n"(n) : "memory")

// ---------------------------------------------------------------------------
// TF32 mma.sync GEMM: C[e][m][n] = act( sum_k A[e][m][k]*B[e][k][n] + bias[e][n] )
// Block tile 128(M) x 256(N), BK=32, 256 threads = 8 warps (2x4), warp 64x64.
// 4-stage cp.async.cg pipeline (208896 B smem). Operands tf32-exact in GMEM.
// Smem: As[m][36] (frag bank = (36*qr+qc)%32 = 4qr+qc -> all 32 distinct),
//       Bs[k][264] (frag bank = (8qc+qr)%32 -> all distinct).
// Inner loop: 4 k8-halves, cross-half fragment ping-pong (prefetch next half's
// fragments while current half's mmas issue). BK=32 halves the number of
// barrier epochs vs BK=16 (the R10 bottleneck).
// ---------------------------------------------------------------------------
#define BK     32
#define AP     36           // As row stride (words)
#define BP     264          // Bs row stride (words)
#define NSTG   4
#define A_STG  (128 * AP * 4)       // 18432 B per stage
#define B_STG  (BK * BP * 4)       // 33792 B per stage
#define SA_OFF(s)  ((s) * A_STG)
#define SB_OFF(s)  (NSTG * A_STG + (s) * B_STG)
#define SM_TOTAL   (NSTG * A_STG + NSTG * B_STG)   // 208896 B (< 227 KB cap)

template <bool RELU, bool ROUND>
__global__ __launch_bounds__(256, 1)
void tgemm64(const float* __restrict__ A,
             const float* __restrict__ Bm,
             const float* __restrict__ bias,
             float* __restrict__ C,
             int nkt,                 // K / BK  (>= NSTG for unguarded prologue)
             long lda, long ldb, long ldc,
             long strideAe, long strideBe, long strideBiasE, long strideCe)
{
    extern __shared__ char smem[];
    const uint32_t sb = smem_u32(smem);
    const int tid = threadIdx.x;
    const int e   = blockIdx.z;

    A    += (long)e * strideAe + (long)blockIdx.x * 128 * lda;
    Bm   += (long)e * strideBe + (long)blockIdx.y * 256;
    bias += (long)e * strideBiasE + (long)blockIdx.y * 256;
    C    += (long)e * strideCe + (long)blockIdx.x * 128 * ldc + (long)blockIdx.y * 256;

    // warp/lane mapping
    const int w    = tid >> 5;
    const int wm   = w & 1;            // 2 warps in M (64 rows each)
    const int wn   = w >> 1;           // 4 warps in N (64 cols each)
    const int lane = tid & 31;
    const int qr   = lane >> 2;        // 0..7
    const int qc   = lane & 3;         // 0..3

    // B staging coords: 8 rows per thread, k = bk + r*4 (r=0..7)
    const int bk = tid >> 6;           // 0..3
    const int bn = (tid & 63) << 2;    // 0..252

    const int mtb0 = wm * 64;
    const int ntb0 = wn * 64;

    float acc[4][8][4];
    #pragma unroll
    for (int i = 0; i < 4; i++)
        #pragma unroll
        for (int j = 0; j < 8; j++)
            #pragma unroll
            for (int r = 0; r < 4; r++) acc[i][j][r] = 0.0f;

    auto issue = [&](int kt, int s) {
        const long ko = (long)kt * BK;
        {
            const uint32_t d0 = sb + SA_OFF(s);
            #pragma unroll
            for (int j = 0; j < 4; j++) {
                const int f  = tid * 4 + j;   // 0..1023 covers all 128x8 chunks
                const int m  = f >> 3;
                const int kq = f & 7;
                cp_async16(d0 + (uint32_t)(m * AP + kq * 4) * 4,
                           A + (long)m * lda + ko + kq * 4);
            }
        }
        {
            const uint32_t d0 = sb + SB_OFF(s);
            #pragma unroll
            for (int r = 0; r < 8; r++) {
                const int k = bk + r * 4;
                cp_async16(d0 + (uint32_t)(k * BP + bn) * 4, Bm + (ko + k) * ldb + bn);
            }
        }
    };

    // load one k8-half's fragments from stage s at k-offset ks
    auto load_half = [&](int s, int ks, uint32_t aF[4][4], uint32_t bF[8][2]) {
        const uint32_t* uA = (const uint32_t*)(smem + SA_OFF(s));
        const uint32_t* uB = (const uint32_t*)(smem + SB_OFF(s));
        #pragma unroll
        for (int i = 0; i < 4; i++) {
            const int mtb = mtb0 + i * 16;
            aF[i][0] = uA[(mtb + qr)     * AP + ks + qc];
            aF[i][1] = uA[(mtb + qr + 8) * AP + ks + qc];
            aF[i][2] = uA[(mtb + qr)     * AP + ks + qc + 4];
            aF[i][3] = uA[(mtb + qr + 8) * AP + ks + qc + 4];
        }
        #pragma unroll
        for (int j = 0; j < 8; j++) {
            const int ntb = ntb0 + j * 8;
            bF[j][0] = uB[(ks + qc)     * BP + ntb + qr];
            bF[j][1] = uB[(ks + qc + 4) * BP + ntb + qr];
        }
    };

    auto mma_half = [&](const uint32_t aF[4][4], const uint32_t bF[8][2]) {
        #pragma unroll
        for (int i = 0; i < 4; i++)
            #pragma unroll
            for (int j = 0; j < 8; j++) {
                asm volatile(
                    "mma.sync.aligned.m16n8k8.row.col.f32.tf32.tf32.f32 "
                    "{%0,%1,%2,%3}, {%4,%5,%6,%7}, {%8,%9}, {%0,%1,%2,%3};\n"
                    : "+f"(acc[i][j][0]), "+f"(acc[i][j][1]),
                      "+f"(acc[i][j][2]), "+f"(acc[i][j][3])
                    : "r"(aF[i][0]), "r"(aF[i][1]), "r"(aF[i][2]), "r"(aF[i][3]),
                      "r"(bF[j][0]), "r"(bF[j][1]));
            }
    };

    // prologue: stages 0..2 in flight; stages 0,1 landed before loop (nkt >= 4)
    issue(0, 0); CP_COMMIT();
    issue(1, 1); CP_COMMIT();
    issue(2, 2); CP_COMMIT();
    CP_WAIT(1);               // stages 0,1 landed
    __syncthreads();

    uint32_t aC[4][4], bC[8][2];   // current half
    uint32_t aN[4][4], bN[8][2];   // next half (prefetch)
    load_half(0, 0, aC, bC);

    for (int kt = 0; kt < nkt; kt++) {
        const int buf = kt & (NSTG - 1);
        const int nxt = (kt + 1 < nkt) ? ((kt + 1) & (NSTG - 1)) : 0;

        load_half(buf,  8, aN, bN);  mma_half(aC, bC);   // h0 (ks=0)
        load_half(buf, 16, aC, bC);  mma_half(aN, bN);   // h1 (ks=8)
        load_half(buf, 24, aN, bN);  mma_half(aC, bC);   // h2 (ks=16)
        load_half(nxt,  0, aC, bC);  mma_half(aN, bN);   // h3 (ks=24)

        // pipeline maintenance: issue kt+3, confirm stage kt+2 landed
        if (kt + 3 < nkt) issue(kt + 3, (kt + 3) & (NSTG - 1));
        CP_COMMIT();
        CP_WAIT(1);
        __syncthreads();
    }

    // ---- epilogue: bias + relu (+tf32 round) + store ----
    #pragma unroll
    for (int j = 0; j < 8; j++) {
        const int ncol = wn * 64 + j * 8 + 2 * qc;
        const float2 bj = *(const float2*)(bias + ncol);
        #pragma unroll
        for (int i = 0; i < 4; i++) {
            const long r0 = wm * 64 + i * 16 + qr;
            float2 v0, v1;
            v0.x = acc[i][j][0] + bj.x;  v0.y = acc[i][j][1] + bj.y;
            v1.x = acc[i][j][2] + bj.x;  v1.y = acc[i][j][3] + bj.y;
            if (RELU) {
                v0.x = fmaxf(v0.x, 0.0f); v0.y = fmaxf(v0.y, 0.0f);
                v1.x = fmaxf(v1.x, 0.0f); v1.y = fmaxf(v1.y, 0.0f);
            }
            if (ROUND) {
                v0.x = rna_tf32(v0.x); v0.y = rna_tf32(v0.y);
                v1.x = rna_tf32(v1.x); v1.y = rna_tf32(v1.y);
            }
            *(float2*)(C + r0 * ldc + ncol)       = v0;
            *(float2*)(C + (r0 + 8) * ldc + ncol) = v1;
        }
    }
}

// ---------------------------------------------------------------------------
// Pre-pass: tf32-round x, W1, W2, W3 in ONE kernel (segmented).
// ---------------------------------------------------------------------------
#define N4_X   ((long)B_SZ * D_IN / 4)
#define N4_W1  ((long)E_EXP * D_IN * H1_SZ / 4)
#define N4_W2  ((long)E_EXP * H1_SZ * H2_SZ / 4)
#define N4_W3  ((long)E_EXP * H2_SZ * H3_SZ / 4)
#define N4_ALL (N4_X + N4_W1 + N4_W2 + N4_W3)

__global__ __launch_bounds__(256)
void round_all_kernel(const float* __restrict__ x,  float* __restrict__ xr,
                      const float* __restrict__ w1, float* __restrict__ w1r,
                      const float* __restrict__ w2, float* __restrict__ w2r,
                      const float* __restrict__ w3, float* __restrict__ w3r)
{
    long i = (long)blockIdx.x * blockDim.x + threadIdx.x;
    if (i >= N4_ALL) return;
    const float4* src;
    float4* dst;
    long off;
    if (i < N4_X)                       { src = (const float4*)x;  dst = (float4*)xr;  off = i; }
    else if (i < N4_X + N4_W1)          { src = (const float4*)w1; dst = (float4*)w1r; off = i - N4_X; }
    else if (i < N4_X + N4_W1 + N4_W2)  { src = (const float4*)w2; dst = (float4*)w2r; off = i - N4_X - N4_W1; }
    else                                { src = (const float4*)w3; dst = (float4*)w3r; off = i - N4_X - N4_W1 - N4_W2; }
    float4 v = src[off];
    v.x = rna_tf32(v.x); v.y = rna_tf32(v.y);
    v.z = rna_tf32(v.z); v.w = rna_tf32(v.w);
    dst[off] = v;
}

// ---------------------------------------------------------------------------
// Gate kernel (fp32, exact): logits = x @ gate_w, softmax over experts,
// store gates as [B][E][T].
// ---------------------------------------------------------------------------
__global__ __launch_bounds__(256)
void gate_kernel(const float* __restrict__ x,
                 const float* __restrict__ gw,
                 float* __restrict__ gates)
{
    __shared__ float xs[8][D_IN];
    __shared__ float gws[64][32];
    __shared__ float lg[8][32];

    const int tid = threadIdx.x;
    const long b0 = (long)blockIdx.x * 8;

    {
        const float4* xg  = (const float4*)(x + b0 * D_IN);
        float4*       xs4 = (float4*)xs;
        #pragma unroll
        for (int i = tid; i < 8 * D_IN / 4; i += 256) xs4[i] = xg[i];
    }

    const int r = tid >> 5;
    const int c = tid & 31;

    float acc = 0.0f;
    for (int kc = 0; kc < D_IN; kc += 64) {
        __syncthreads();
        const float4* gwg = (const float4*)(gw + (long)kc * 32);
        float4*       gs4 = (float4*)gws;
        for (int i = tid; i < 64 * 32 / 4; i += 256) gs4[i] = gwg[i];
        __syncthreads();
        #pragma unroll
        for (int k = 0; k < 64; k++)
            acc = fmaf(xs[r][kc + k], gws[k][c], acc);
    }

    lg[r][c] = acc;
    __syncthreads();

    const int t  = c >> 3;
    const int base = t << 3;
    const int eI = c & 7;
    float mx = -1e30f;
    #pragma unroll
    for (int j = 0; j < 8; j++) mx = fmaxf(mx, lg[r][base + j]);
    float s = 0.0f;
    #pragma unroll
    for (int j = 0; j < 8; j++) s += expf(lg[r][base + j] - mx);
    float gate = expf(acc - mx) / s;

    gates[(b0 + r) * (E_EXP * T_TASK) + eI * T_TASK + t] = gate;
}

// ---------------------------------------------------------------------------
// Combine: out[t][b][d] = sum_e h3[b][e][d] * gates[b][e][t]
// ---------------------------------------------------------------------------
__global__ __launch_bounds__(128)
void combine_kernel(const float* __restrict__ h3,
                    const float* __restrict__ gates,
                    float* __restrict__ out)
{
    const int  tid = threadIdx.x;
    const long b   = (long)blockIdx.x * 2 + (tid >> 6);
    const int  d4  = (tid & 63);

    __shared__ float g[2][E_EXP * T_TASK];
    if (tid < 2 * E_EXP * T_TASK)
        g[tid >> 5][tid & 31] =
            gates[((long)blockIdx.x * 2 + (tid >> 5)) * (E_EXP * T_TASK) + (tid & 31)];
    __syncthreads();

    const int rsel = tid >> 6;
    float4 a0 = {0,0,0,0}, a1 = {0,0,0,0}, a2 = {0,0,0,0}, a3 = {0,0,0,0};
    #pragma unroll
    for (int e = 0; e < E_EXP; e++) {
        float4 v = *(const float4*)(h3 + ((b * E_EXP + e) * H3_SZ) + d4 * 4);
        const float g0 = g[rsel][e * T_TASK + 0];
        const float g1 = g[rsel][e * T_TASK + 1];
        const float g2 = g[rsel][e * T_TASK + 2];
        const float g3 = g[rsel][e * T_TASK + 3];
        a0.x = fmaf(v.x, g0, a0.x); a0.y = fmaf(v.y, g0, a0.y);
        a0.z = fmaf(v.z, g0, a0.z); a0.w = fmaf(v.w, g0, a0.w);
        a1.x = fmaf(v.x, g1, a1.x); a1.y = fmaf(v.y, g1, a1.y);
        a1.z = fmaf(v.z, g1, a1.z); a1.w = fmaf(v.w, g1, a1.w);
        a2.x = fmaf(v.x, g2, a2.x); a2.y = fmaf(v.y, g2, a2.y);
        a2.z = fmaf(v.z, g2, a2.z); a2.w = fmaf(v.w, g2, a2.w);
        a3.x = fmaf(v.x, g3, a3.x); a3.y = fmaf(v.y, g3, a3.y);
        a3.z = fmaf(v.z, g3, a3.z); a3.w = fmaf(v.w, g3, a3.w);
    }
    const long base = b * H3_SZ + d4 * 4;
    const long ts   = (long)B_SZ * H3_SZ;
    *(float4*)(out + 0 * ts + base) = a0;
    *(float4*)(out + 1 * ts + base) = a1;
    *(float4*)(out + 2 * ts + base) = a2;
    *(float4*)(out + 3 * ts + base) = a3;
}

// ---------------------------------------------------------------------------
extern "C" void kernel_launch(void* const* d_in, const int* in_sizes, int n_in,
                              void* d_out, int out_size)
{
    const float* x      = (const float*)d_in[0];
    const float* W1     = (const float*)d_in[1];
    const float* b1     = (const float*)d_in[2];
    const float* W2     = (const float*)d_in[3];
    const float* b2     = (const float*)d_in[4];
    const float* W3     = (const float*)d_in[5];
    const float* b3     = (const float*)d_in[6];
    const float* gate_w = (const float*)d_in[7];
    float* out = (float*)d_out;

    float *h1, *h2, *h3, *gates, *xr, *w1r, *w2r, *w3r;
    cudaGetSymbolAddress((void**)&h1,    g_h1);
    cudaGetSymbolAddress((void**)&h2,    g_h2);
    cudaGetSymbolAddress((void**)&h3,    g_h3);
    cudaGetSymbolAddress((void**)&gates, g_gates);
    cudaGetSymbolAddress((void**)&xr,    g_xr);
    cudaGetSymbolAddress((void**)&w1r,   g_w1r);
    cudaGetSymbolAddress((void**)&w2r,   g_w2r);
    cudaGetSymbolAddress((void**)&w3r,   g_w3r);

    cudaFuncSetAttribute(tgemm64<true, true>,
                         cudaFuncAttributeMaxDynamicSharedMemorySize, SM_TOTAL);
    cudaFuncSetAttribute(tgemm64<true, false>,
                         cudaFuncAttributeMaxDynamicSharedMemorySize, SM_TOTAL);

    // Pre-pass: tf32-round x and all weights in one launch
    round_all_kernel<<<(int)((N4_ALL + 255) / 256), 256>>>(
        x, xr, W1, w1r, W2, w2r, W3, w3r);

    // Gates (fp32, reads original x)
    gate_kernel<<<B_SZ / 8, 256>>>(x, gate_w, gates);

    // Layer 1: h1 = round(relu(xr @ W1 + b1))   nkt = 1024/32 = 32
    {
        dim3 grid(B_SZ / 128, H1_SZ / 256, E_EXP);
        tgemm64<true, true><<<grid, 256, SM_TOTAL>>>(
            xr, w1r, b1, h1, D_IN / BK,
            /*lda*/ D_IN, /*ldb*/ H1_SZ, /*ldc*/ (long)E_EXP * H1_SZ,
            /*strideAe*/ 0, /*strideBe*/ (long)D_IN * H1_SZ,
            /*strideBiasE*/ H1_SZ, /*strideCe*/ H1_SZ);
    }

    // Layer 2: h2 = round(relu(h1 @ W2 + b2))   nkt = 32
    {
        dim3 grid(B_SZ / 128, H2_SZ / 256, E_EXP);
        tgemm64<true, true><<<grid, 256, SM_TOTAL>>>(
            h1, w2r, b2, h2, H1_SZ / BK,
            /*lda*/ (long)E_EXP * H1_SZ, /*ldb*/ H2_SZ, /*ldc*/ (long)E_EXP * H2_SZ,
            /*strideAe*/ H1_SZ, /*strideBe*/ (long)H1_SZ * H2_SZ,
            /*strideBiasE*/ H2_SZ, /*strideCe*/ H2_SZ);
    }

    // Layer 3: h3 = relu(h2 @ W3 + b3)          nkt = 16
    {
        dim3 grid(B_SZ / 128, H3_SZ / 256, E_EXP);
        tgemm64<true, false><<<grid, 256, SM_TOTAL>>>(
            h2, w3r, b3, h3, H2_SZ / BK,
            /*lda*/ (long)E_EXP * H2_SZ, /*ldb*/ H3_SZ, /*ldc*/ (long)E_EXP * H3_SZ,
            /*strideAe*/ H2_SZ, /*strideBe*/ (long)H2_SZ * H3_SZ,
            /*strideBiasE*/ H3_SZ, /*strideCe*/ H3_SZ);
    }

    // Combine with gates
    combine_kernel<<<B_SZ / 2, 128>>>(h3, gates, out);
}